// round 15
// baseline (speedup 1.0000x reference)
#include <cuda_runtime.h>
#include <cstdint>

// ---------------------------------------------------------------------------
// TrivialTreeTagger: B=32768, 5 tree-LSTM blocks (H=64,E=32).
// last = relu(h3)*(s==4): only s==4 elements (~25%) need LSTM work.
// R14: R13 (16 warps x 4 rows, cp.async staging, double-buffered xp) with
// TWO-PASS gates (i,f then g,o): 16 u64 acc per pass -> ~100 regs, real
// headroom at 4 warps/SMSP for load batching / latency hiding.
// tcgen05 unavailable: harness PTX target is sm_103 (no 'a').
// ---------------------------------------------------------------------------

#define MAXB 32768

struct Counters { int act; int triv; };
__device__ Counters g_cnt;
__device__ int g_idx[MAXB];
__device__ int g_tidx[MAXB];

typedef unsigned long long u64;
typedef unsigned int u32;

__device__ __forceinline__ float ftanh_(float x) {
    float r; asm("tanh.approx.f32 %0, %1;" : "=f"(r) : "f"(x)); return r;
}
__device__ __forceinline__ float fsig(float x) {
    return fmaf(0.5f, ftanh_(0.5f * x), 0.5f);
}
__device__ __forceinline__ void ffma2(u64& a, u64 b, u64 c) {
    asm("fma.rn.f32x2 %0, %1, %2, %0;" : "+l"(a) : "l"(b), "l"(c));
}
__device__ __forceinline__ u64 packf2(float lo, float hi) {
    u64 r; asm("mov.b64 %0, {%1, %2};" : "=l"(r) : "f"(lo), "f"(hi)); return r;
}
__device__ __forceinline__ float hsum2(u64 v) {
    float lo, hi; asm("mov.b64 {%0, %1}, %2;" : "=f"(lo), "=f"(hi) : "l"(v));
    return lo + hi;
}
__device__ __forceinline__ u32 smem_u32(const void* p) {
    u32 a; asm("{ .reg .u64 t; cvta.to.shared.u64 t, %1; cvt.u32.u64 %0, t; }"
               : "=r"(a) : "l"(p));
    return a;
}
__device__ __forceinline__ void cpa8(u32 dst, const void* src) {
    asm volatile("cp.async.ca.shared.global [%0], [%1], 8;" :: "r"(dst), "l"(src));
}
#define CPA_COMMIT() asm volatile("cp.async.commit_group;" ::: "memory")
#define CPA_WAIT0()  asm volatile("cp.async.wait_group 0;" ::: "memory")

__device__ __forceinline__ void load32(float (&dst)[32], const float* __restrict__ src) {
    const float4* p = reinterpret_cast<const float4*>(src);
#pragma unroll
    for (int c = 0; c < 8; ++c) {
        float4 v = p[c];
        dst[4*c] = v.x; dst[4*c+1] = v.y; dst[4*c+2] = v.z; dst[4*c+3] = v.w;
    }
}

// -------------------- kernel 1: compaction ----------------------------------
__global__ void __launch_bounds__(256) k_compact(const int* __restrict__ s, int B)
{
    int i = blockIdx.x * 256 + threadIdx.x;
    bool valid = i < B;
    bool a = valid && (s[i] == 4);
    bool t = valid && !a;
    unsigned ba = __ballot_sync(0xffffffffu, a);
    unsigned bt = __ballot_sync(0xffffffffu, t);
    int lane = threadIdx.x & 31;
    if (a) {
        int leader = __ffs(ba) - 1;
        int pos = 0;
        if (lane == leader) pos = atomicAdd(&g_cnt.act, __popc(ba));
        pos = __shfl_sync(ba, pos, leader);
        g_idx[pos + __popc(ba & ((1u << lane) - 1))] = i;
    } else if (t) {
        int leader = __ffs(bt) - 1;
        int pos = 0;
        if (lane == leader) pos = atomicAdd(&g_cnt.triv, __popc(bt));
        pos = __shfl_sync(bt, pos, leader);
        g_tidx[pos + __popc(bt & ((1u << lane) - 1))] = i;
    }
}

// -------------------- kernel 2: fused main ----------------------------------
struct SmemB {
    ulonglong2 Wif[48][64];  // [kk][j] = (i K-pair, f K-pair)   48KB
    ulonglong2 Wgo[48][64];  // [kk][j] = (g K-pair, o K-pair)   48KB
    u64  Wc2[32 * 48];
    u64  Wt2[64 * 16];
    float2 bIF[64], bGO[64];
    float2 a0IF[64], a0GO[64];
    float c0s[64];
    float bc[32];
    float bt[64];
    u64  hp[32][64];         // h pairs [kpair][e], single buffer
    u64  xp[2][16][64];      // x pairs DOUBLE buffer [buf][kpair][e]
    u64  xroot[16][64];      // root emb pairs; epilogue scratch
    u64  xbig[5][16][64];    // comb outputs per bp, pair layout
};

// One gate-pair pass: 4 rows x (lo,hi gates) x 2 elems -> 16 u64 acc.
__device__ __forceinline__ void gate_pass4(
    const ulonglong2* __restrict__ wbase,   // &W[0][j0]
    const u64* __restrict__ xops, const u64* __restrict__ hops,
    int e0, int e1, bool do_h,
    const float2* __restrict__ pre, int j0,
    float (&glo)[4][2], float (&ghi)[4][2])
{
    u64 aL[4][2], aH[4][2];
#pragma unroll
    for (int r = 0; r < 4; ++r) {
        float2 pv = pre[j0 + r];
        aL[r][0] = packf2(pv.x, 0.f); aL[r][1] = aL[r][0];
        aH[r][0] = packf2(pv.y, 0.f); aH[r][1] = aH[r][0];
    }
#pragma unroll 4
    for (int kk = 0; kk < 16; ++kk) {
        u64 oA = xops[kk*64 + e0], oB = xops[kk*64 + e1];
        const ulonglong2* wp = wbase + kk*64;
#pragma unroll
        for (int r = 0; r < 4; ++r) {
            ulonglong2 wv = wp[r];
            ffma2(aL[r][0], wv.x, oA); ffma2(aH[r][0], wv.y, oA);
            ffma2(aL[r][1], wv.x, oB); ffma2(aH[r][1], wv.y, oB);
        }
    }
    if (do_h) {
#pragma unroll 4
        for (int kk = 0; kk < 32; ++kk) {
            u64 oA = hops[kk*64 + e0], oB = hops[kk*64 + e1];
            const ulonglong2* wp = wbase + (16 + kk)*64;
#pragma unroll
            for (int r = 0; r < 4; ++r) {
                ulonglong2 wv = wp[r];
                ffma2(aL[r][0], wv.x, oA); ffma2(aH[r][0], wv.y, oA);
                ffma2(aL[r][1], wv.x, oB); ffma2(aH[r][1], wv.y, oB);
            }
        }
    }
#pragma unroll
    for (int r = 0; r < 4; ++r) {
        glo[r][0] = hsum2(aL[r][0]); glo[r][1] = hsum2(aL[r][1]);
        ghi[r][0] = hsum2(aH[r][0]); ghi[r][1] = hsum2(aH[r][1]);
    }
}

__global__ void __launch_bounds__(512, 1) k_main(
    const int* __restrict__ x, const float* __restrict__ emb,
    const float* __restrict__ Wih, const float* __restrict__ Whh,
    const float* __restrict__ bih, const float* __restrict__ bhh,
    const float* __restrict__ h0, const float* __restrict__ c0,
    const float* __restrict__ Wc, const float* __restrict__ bcv,
    const float* __restrict__ Wt, const float* __restrict__ btv,
    float* __restrict__ out, int B)
{
    int cnt = g_cnt.act;
    int nl = (cnt + 63) >> 6;
    int tid = threadIdx.x;

    if ((int)blockIdx.x >= nl) {
        // -------------------- trivial path (idle blocks) --------------------
        int tcnt = g_cnt.triv;
        int ntriv = gridDim.x - nl;
        for (int c = blockIdx.x - nl; c * 512 < tcnt; c += ntriv) {
            int ti = c * 512 + tid;
            if (ti >= tcnt) continue;
            int i = g_tidx[ti];
            float r[32];
            load32(r, emb + (size_t)x[i * 16] * 32);
            float cb[32];
#pragma unroll
            for (int m = 0; m < 32; ++m) {
                float acc = bcv[m];
                const float4* wv4 = reinterpret_cast<const float4*>(Wc + m * 96);
#pragma unroll
                for (int k = 0; k < 8; ++k) {
                    float4 wv = wv4[k];
                    acc = fmaf(wv.x, r[4*k], acc);   acc = fmaf(wv.y, r[4*k+1], acc);
                    acc = fmaf(wv.z, r[4*k+2], acc); acc = fmaf(wv.w, r[4*k+3], acc);
                }
                cb[m] = fmaxf(acc, 0.0f);
            }
            float lg[64], mx = -1e30f;
#pragma unroll
            for (int m = 0; m < 64; ++m) {
                float acc = btv[m];
                const float4* wv4 = reinterpret_cast<const float4*>(Wt + m * 32);
#pragma unroll
                for (int k = 0; k < 8; ++k) {
                    float4 wv = wv4[k];
                    acc = fmaf(wv.x, cb[4*k], acc);   acc = fmaf(wv.y, cb[4*k+1], acc);
                    acc = fmaf(wv.z, cb[4*k+2], acc); acc = fmaf(wv.w, cb[4*k+3], acc);
                }
                lg[m] = acc; mx = fmaxf(mx, acc);
            }
            float se = 0.0f;
#pragma unroll
            for (int m = 0; m < 64; ++m) se += __expf(lg[m] - mx);
            float lse = mx + logf(se);
            float4* o4 = reinterpret_cast<float4*>(out + (size_t)i * 64);
#pragma unroll
            for (int cc = 0; cc < 16; ++cc) {
                float4 v;
                v.x = lg[4*cc]-lse; v.y = lg[4*cc+1]-lse;
                v.z = lg[4*cc+2]-lse; v.w = lg[4*cc+3]-lse;
                o4[cc] = v;
            }
        }
        return;
    }

    // ------------------------- LSTM path ------------------------------------
    extern __shared__ char smraw[];
    SmemB* sm = reinterpret_cast<SmemB*>(smraw);

    int lane = tid & 31;
    int w = tid >> 5;          // 0..15
    int j0 = w * 4;            // 4 rows per warp
    int e0 = lane, e1 = lane + 32;
    int gA = blockIdx.x * 64 + e0, gB = gA + 32;
    bool actA = gA < cnt, actB = gB < cnt;
    int iA = g_idx[actA ? gA : (cnt - 1)];
    int iB = g_idx[actB ? gB : (cnt - 1)];

    // x stager identity (tid<256): 4 threads/elem, pg = 8-float chunk
    int ep = tid & 63, pg = (tid >> 6) & 3;
    bool stager = tid < 256;
    int gp = blockIdx.x * 64 + ep;
    const int* xrP = x + (size_t)g_idx[gp < cnt ? gp : (cnt - 1)] * 16;

    u32 xpbase = smem_u32(&sm->xp[0][0][0]);
    u32 xrbase = smem_u32(&sm->xroot[0][0]);
    u32 stoff = ((pg * 4) * 64 + ep) * 8;   // this thread's 4 kpair slots

    // stage step-0 x into xp[0] via cp.async
    if (stager) {
        const char* src = (const char*)emb + (size_t)xrP[0] * 128 + pg * 32;
        u32 dst = xpbase + stoff;
#pragma unroll
        for (int c = 0; c < 4; ++c) cpa8(dst + c * 512, src + c * 8);
        CPA_COMMIT();
    }

    // ---- shared init (weights etc.) ----
    for (int idx = tid; idx < 48 * 64; idx += 512) {
        int kk = idx >> 6, j = idx & 63;
        float wi0, wi1, wf0, wf1, wg0, wg1, wo0, wo1;
        if (kk < 16) {
            int c = 2*kk;
            wi0 = Wih[j*32 + c];          wi1 = Wih[j*32 + c + 1];
            wf0 = Wih[(64 + j)*32 + c];   wf1 = Wih[(64 + j)*32 + c + 1];
            wg0 = Wih[(128 + j)*32 + c];  wg1 = Wih[(128 + j)*32 + c + 1];
            wo0 = Wih[(192 + j)*32 + c];  wo1 = Wih[(192 + j)*32 + c + 1];
        } else {
            int c = 2*kk - 32;
            wi0 = Whh[j*64 + c];          wi1 = Whh[j*64 + c + 1];
            wf0 = Whh[(64 + j)*64 + c];   wf1 = Whh[(64 + j)*64 + c + 1];
            wg0 = Whh[(128 + j)*64 + c];  wg1 = Whh[(128 + j)*64 + c + 1];
            wo0 = Whh[(192 + j)*64 + c];  wo1 = Whh[(192 + j)*64 + c + 1];
        }
        ulonglong2 vif, vgo;
        vif.x = packf2(wi0, wi1); vif.y = packf2(wf0, wf1);
        vgo.x = packf2(wg0, wg1); vgo.y = packf2(wo0, wo1);
        sm->Wif[kk][j] = vif;
        sm->Wgo[kk][j] = vgo;
    }
    if (tid < 64) {
        int j = tid;
        float bi = bih[j] + bhh[j];
        float bf = bih[64 + j] + bhh[64 + j];
        float bg = bih[128 + j] + bhh[128 + j];
        float bo = bih[192 + j] + bhh[192 + j];
        float ai = bi, af = bf, ag = bg, ao = bo;
        for (int k = 0; k < 64; ++k) {
            float hk = h0[k];
            ai = fmaf(Whh[j*64 + k], hk, ai);
            af = fmaf(Whh[(64 + j)*64 + k], hk, af);
            ag = fmaf(Whh[(128 + j)*64 + k], hk, ag);
            ao = fmaf(Whh[(192 + j)*64 + k], hk, ao);
        }
        sm->bIF[j]  = make_float2(bi, bf);
        sm->bGO[j]  = make_float2(bg, bo);
        sm->a0IF[j] = make_float2(ai, af);
        sm->a0GO[j] = make_float2(ag, ao);
        sm->c0s[j] = c0[j];
        sm->bt[j] = btv[j];
    }
    for (int idx = tid; idx < 32 * 48; idx += 512) {
        int m = idx / 48, kk = idx % 48;
        sm->Wc2[idx] = packf2(Wc[m*96 + 2*kk], Wc[m*96 + 2*kk + 1]);
    }
    for (int idx = tid; idx < 64 * 16; idx += 512) {
        int m = idx / 16, kk = idx % 16;
        sm->Wt2[idx] = packf2(Wt[m*32 + 2*kk], Wt[m*32 + 2*kk + 1]);
    }
    if (tid < 32) sm->bc[tid] = bcv[tid];
    CPA_WAIT0();
    __syncthreads();

    float cA[4], cB[4];

#pragma unroll 1
    for (int bp = 0; bp < 5; ++bp) {
#pragma unroll 1
        for (int t = 0; t < 4; ++t) {
            int step = 4*bp + t;
            int b = step & 1;

            // stagers: async-stage next x into the OTHER xp buffer
            if (stager && step + 1 < 16) {
                const char* src = (const char*)emb + (size_t)xrP[step + 1] * 128 + pg * 32;
                u32 dst = xpbase + (u32)(((step + 1) & 1) * 8192) + stoff;
#pragma unroll
                for (int c = 0; c < 4; ++c) cpa8(dst + c * 512, src + c * 8);
                CPA_COMMIT();
            }
            // bp4 root = emb[x[0]] -> xroot (async)
            if (stager && bp == 4 && t == 0) {
                const char* src = (const char*)emb + (size_t)xrP[0] * 128 + pg * 32;
                u32 dst = xrbase + stoff;
#pragma unroll
                for (int c = 0; c < 4; ++c) cpa8(dst + c * 512, src + c * 8);
                CPA_COMMIT();
            }

            const u64* ops = (bp < 4) ? &sm->xp[b][0][0] : &sm->xbig[t][0][0];
            const u64* hrd = &sm->hp[0][0];

            // ---- two gate passes: (i,f) then (g,o) ----
            float gi[4][2], gf[4][2], gg[4][2], go_[4][2];
            gate_pass4(&sm->Wif[0][j0], ops, hrd, e0, e1, t > 0,
                       (t == 0) ? sm->a0IF : sm->bIF, j0, gi, gf);
            gate_pass4(&sm->Wgo[0][j0], ops, hrd, e0, e1, t > 0,
                       (t == 0) ? sm->a0GO : sm->bGO, j0, gg, go_);
            __syncthreads();   // sync1: all xp/hp reads done

            // activations + c update + h write
            float* hwf = reinterpret_cast<float*>(&sm->hp[0][0]);
#pragma unroll
            for (int r = 0; r < 4; ++r) {
                int j = j0 + r;
                {
                    float iv = fsig(gi[r][0]);
                    float fv = fsig(gf[r][0]);
                    float gv = ftanh_(gg[r][0]);
                    float ov = fsig(go_[r][0]);
                    float cp = (t == 0) ? sm->c0s[j] : cA[r];
                    float cc = fmaf(fv, cp, iv * gv);
                    cA[r] = cc;
                    float hn = ov * ftanh_(cc);
                    hwf[((j >> 1)*64 + e0)*2 + (j & 1)] = (t == 3) ? fmaxf(hn, 0.f) : hn;
                }
                {
                    float iv = fsig(gi[r][1]);
                    float fv = fsig(gf[r][1]);
                    float gv = ftanh_(gg[r][1]);
                    float ov = fsig(go_[r][1]);
                    float cp = (t == 0) ? sm->c0s[j] : cB[r];
                    float cc = fmaf(fv, cp, iv * gv);
                    cB[r] = cc;
                    float hn = ov * ftanh_(cc);
                    hwf[((j >> 1)*64 + e1)*2 + (j & 1)] = (t == 3) ? fmaxf(hn, 0.f) : hn;
                }
            }
            // root snapshot: copy CURRENT x (xp[0], b==0 at t==0) -> xroot.
            // cp.async this step writes xp[1]; no overlap.
            if (t == 0 && bp < 4 && stager) {
                const u64* s0 = &sm->xp[0][0][0];
                u64* d0 = &sm->xroot[0][0];
#pragma unroll
                for (int c = 0; c < 4; ++c) d0[tid*4 + c] = s0[tid*4 + c];
            }
            CPA_WAIT0();       // next-x (and bp4 root) landed
            __syncthreads();   // sync2: hp/xp/xroot ready
        }

        // ---- comb = relu(Wc @ [root, last] + bc); 16 warps x 2 rows ----
        {
            int m0 = w * 2;
            u64 ac[2][2];
#pragma unroll
            for (int mr = 0; mr < 2; ++mr) {
                ac[mr][0] = packf2(sm->bc[m0 + mr], 0.f);
                ac[mr][1] = ac[mr][0];
            }
            const u64* xr_ = &sm->xroot[0][0];
#pragma unroll 4
            for (int kk = 0; kk < 16; ++kk) {
                u64 oA = xr_[kk*64 + e0], oB = xr_[kk*64 + e1];
#pragma unroll
                for (int mr = 0; mr < 2; ++mr) {
                    u64 wv = sm->Wc2[(m0 + mr)*48 + kk];
                    ffma2(ac[mr][0], wv, oA); ffma2(ac[mr][1], wv, oB);
                }
            }
            const u64* hrd = &sm->hp[0][0];
#pragma unroll 4
            for (int kk = 0; kk < 32; ++kk) {
                u64 oA = hrd[kk*64 + e0], oB = hrd[kk*64 + e1];
#pragma unroll
                for (int mr = 0; mr < 2; ++mr) {
                    u64 wv = sm->Wc2[(m0 + mr)*48 + 16 + kk];
                    ffma2(ac[mr][0], wv, oA); ffma2(ac[mr][1], wv, oB);
                }
            }
            float* xbf = reinterpret_cast<float*>(&sm->xbig[bp][0][0]);
#pragma unroll
            for (int mr = 0; mr < 2; ++mr) {
                int m = m0 + mr;
                xbf[((m >> 1)*64 + e0)*2 + (m & 1)] = fmaxf(hsum2(ac[mr][0]), 0.f);
                xbf[((m >> 1)*64 + e1)*2 + (m & 1)] = fmaxf(hsum2(ac[mr][1]), 0.f);
            }
            __syncthreads();
        }
    }

    // ---- logits + log_softmax (4 tags per warp) ----
    {
        int m0 = w * 4;
        u64 lA[4], lB[4];
#pragma unroll
        for (int mr = 0; mr < 4; ++mr) {
            lA[mr] = packf2(sm->bt[m0 + mr], 0.f);
            lB[mr] = lA[mr];
        }
        const u64* cbr = &sm->xbig[4][0][0];
#pragma unroll 4
        for (int kk = 0; kk < 16; ++kk) {
            u64 oA = cbr[kk*64 + e0], oB = cbr[kk*64 + e1];
#pragma unroll
            for (int mr = 0; mr < 4; ++mr) {
                u64 wv = sm->Wt2[(m0 + mr)*16 + kk];
                ffma2(lA[mr], wv, oA); ffma2(lB[mr], wv, oB);
            }
        }
        float lgA[4], lgB[4], mxA = -1e30f, mxB = -1e30f;
#pragma unroll
        for (int mr = 0; mr < 4; ++mr) {
            lgA[mr] = hsum2(lA[mr]); mxA = fmaxf(mxA, lgA[mr]);
            lgB[mr] = hsum2(lB[mr]); mxB = fmaxf(mxB, lgB[mr]);
        }
        float* red = reinterpret_cast<float*>(&sm->xroot[0][0]);
        red[w*64 + e0] = mxA;
        red[w*64 + e1] = mxB;
        __syncthreads();
        float fmxA = -1e30f, fmxB = -1e30f;
#pragma unroll
        for (int k = 0; k < 16; ++k) {
            fmxA = fmaxf(fmxA, red[k*64 + e0]);
            fmxB = fmaxf(fmxB, red[k*64 + e1]);
        }
        float seA = 0.f, seB = 0.f;
#pragma unroll
        for (int mr = 0; mr < 4; ++mr) {
            seA += __expf(lgA[mr] - fmxA);
            seB += __expf(lgB[mr] - fmxB);
        }
        red[1024 + w*64 + e0] = seA;
        red[1024 + w*64 + e1] = seB;
        __syncthreads();
        float tseA = 0.f, tseB = 0.f;
#pragma unroll
        for (int k = 0; k < 16; ++k) {
            tseA += red[1024 + k*64 + e0];
            tseB += red[1024 + k*64 + e1];
        }
        float lseA = fmxA + logf(tseA);
        float lseB = fmxB + logf(tseB);
        if (actA) {
            float4 v;
            v.x = lgA[0]-lseA; v.y = lgA[1]-lseA; v.z = lgA[2]-lseA; v.w = lgA[3]-lseA;
            *reinterpret_cast<float4*>(out + (size_t)iA * 64 + m0) = v;
        }
        if (actB) {
            float4 v;
            v.x = lgB[0]-lseB; v.y = lgB[1]-lseB; v.z = lgB[2]-lseB; v.w = lgB[3]-lseB;
            *reinterpret_cast<float4*>(out + (size_t)iB * 64 + m0) = v;
        }
    }
}

// ---------------------------------------------------------------------------
extern "C" void kernel_launch(void* const* d_in, const int* in_sizes, int n_in,
                              void* d_out, int out_size)
{
    const int*   x   = (const int*)d_in[0];
    const int*   s   = (const int*)d_in[1];
    const float* emb = (const float*)d_in[2];
    const float* Wih = (const float*)d_in[3];
    const float* Whh = (const float*)d_in[4];
    const float* bih = (const float*)d_in[5];
    const float* bhh = (const float*)d_in[6];
    const float* h0  = (const float*)d_in[7];
    const float* c0  = (const float*)d_in[8];
    const float* Wc  = (const float*)d_in[9];
    const float* bc  = (const float*)d_in[10];
    const float* Wt  = (const float*)d_in[11];
    const float* bt  = (const float*)d_in[12];
    float* out = (float*)d_out;

    int B = in_sizes[1];
    if (B > MAXB) B = MAXB;

    cudaFuncSetAttribute(k_main, cudaFuncAttributeMaxDynamicSharedMemorySize,
                         (int)sizeof(SmemB));

    void* cptr = nullptr;
    cudaGetSymbolAddress(&cptr, g_cnt);
    cudaMemsetAsync(cptr, 0, sizeof(Counters));

    k_compact<<<(B + 255) / 256, 256>>>(s, B);
    int nblk = (B + 63) / 64;
    k_main<<<nblk, 512, sizeof(SmemB)>>>(x, emb, Wih, Whh, bih, bhh,
                                         h0, c0, Wc, bc, Wt, bt, out, B);
}

// round 16
// speedup vs baseline: 1.0802x; 1.0802x over previous
#include <cuda_runtime.h>
#include <cstdint>

// ---------------------------------------------------------------------------
// TrivialTreeTagger: B=32768, 5 tree-LSTM blocks (H=64,E=32).
// last = relu(h3)*(s==4): only s==4 elements (~25%) need LSTM work.
// R15: R13 (16 warps x 4 rows, fused gates, cp.async staging, double-buffered
// xp) + DOUBLE-BUFFERED hp -> ONE __syncthreads per step (was 2). Removes the
// WAR hazard that forced sync1; barriers drop 45 -> 25.
// tcgen05 unavailable: harness PTX target is sm_103 (no 'a').
// ---------------------------------------------------------------------------

#define MAXB 32768

struct Counters { int act; int triv; };
__device__ Counters g_cnt;
__device__ int g_idx[MAXB];
__device__ int g_tidx[MAXB];

typedef unsigned long long u64;
typedef unsigned int u32;

__device__ __forceinline__ float ftanh_(float x) {
    float r; asm("tanh.approx.f32 %0, %1;" : "=f"(r) : "f"(x)); return r;
}
__device__ __forceinline__ float fsig(float x) {
    return fmaf(0.5f, ftanh_(0.5f * x), 0.5f);
}
__device__ __forceinline__ void ffma2(u64& a, u64 b, u64 c) {
    asm("fma.rn.f32x2 %0, %1, %2, %0;" : "+l"(a) : "l"(b), "l"(c));
}
__device__ __forceinline__ u64 packf2(float lo, float hi) {
    u64 r; asm("mov.b64 %0, {%1, %2};" : "=l"(r) : "f"(lo), "f"(hi)); return r;
}
__device__ __forceinline__ float hsum2(u64 v) {
    float lo, hi; asm("mov.b64 {%0, %1}, %2;" : "=f"(lo), "=f"(hi) : "l"(v));
    return lo + hi;
}
__device__ __forceinline__ u32 smem_u32(const void* p) {
    u32 a; asm("{ .reg .u64 t; cvta.to.shared.u64 t, %1; cvt.u32.u64 %0, t; }"
               : "=r"(a) : "l"(p));
    return a;
}
__device__ __forceinline__ void cpa8(u32 dst, const void* src) {
    asm volatile("cp.async.ca.shared.global [%0], [%1], 8;" :: "r"(dst), "l"(src));
}
#define CPA_COMMIT() asm volatile("cp.async.commit_group;" ::: "memory")
#define CPA_WAIT0()  asm volatile("cp.async.wait_group 0;" ::: "memory")

__device__ __forceinline__ void load32(float (&dst)[32], const float* __restrict__ src) {
    const float4* p = reinterpret_cast<const float4*>(src);
#pragma unroll
    for (int c = 0; c < 8; ++c) {
        float4 v = p[c];
        dst[4*c] = v.x; dst[4*c+1] = v.y; dst[4*c+2] = v.z; dst[4*c+3] = v.w;
    }
}

// -------------------- kernel 1: compaction ----------------------------------
__global__ void __launch_bounds__(256) k_compact(const int* __restrict__ s, int B)
{
    int i = blockIdx.x * 256 + threadIdx.x;
    bool valid = i < B;
    bool a = valid && (s[i] == 4);
    bool t = valid && !a;
    unsigned ba = __ballot_sync(0xffffffffu, a);
    unsigned bt = __ballot_sync(0xffffffffu, t);
    int lane = threadIdx.x & 31;
    if (a) {
        int leader = __ffs(ba) - 1;
        int pos = 0;
        if (lane == leader) pos = atomicAdd(&g_cnt.act, __popc(ba));
        pos = __shfl_sync(ba, pos, leader);
        g_idx[pos + __popc(ba & ((1u << lane) - 1))] = i;
    } else if (t) {
        int leader = __ffs(bt) - 1;
        int pos = 0;
        if (lane == leader) pos = atomicAdd(&g_cnt.triv, __popc(bt));
        pos = __shfl_sync(bt, pos, leader);
        g_tidx[pos + __popc(bt & ((1u << lane) - 1))] = i;
    }
}

// -------------------- kernel 2: fused main ----------------------------------
struct SmemB {
    ulonglong2 Wif[48][64];  // [kk][j] = (i K-pair, f K-pair)   48KB
    ulonglong2 Wgo[48][64];  // [kk][j] = (g K-pair, o K-pair)   48KB
    u64  Wc2[32 * 48];
    u64  Wt2[64 * 16];
    float2 bIF[64], bGO[64];
    float2 a0IF[64], a0GO[64];
    float c0s[64];
    float bc[32];
    float bt[64];
    u64  hp[2][32][64];      // h pairs DOUBLE buffer [buf][kpair][e]
    u64  xp[2][16][64];      // x pairs DOUBLE buffer [buf][kpair][e]
    u64  xroot[16][64];      // root emb pairs; epilogue scratch
    u64  xbig[5][16][64];    // comb outputs per bp, pair layout
};

__global__ void __launch_bounds__(512, 1) k_main(
    const int* __restrict__ x, const float* __restrict__ emb,
    const float* __restrict__ Wih, const float* __restrict__ Whh,
    const float* __restrict__ bih, const float* __restrict__ bhh,
    const float* __restrict__ h0, const float* __restrict__ c0,
    const float* __restrict__ Wc, const float* __restrict__ bcv,
    const float* __restrict__ Wt, const float* __restrict__ btv,
    float* __restrict__ out, int B)
{
    int cnt = g_cnt.act;
    int nl = (cnt + 63) >> 6;
    int tid = threadIdx.x;

    if ((int)blockIdx.x >= nl) {
        // -------------------- trivial path (idle blocks) --------------------
        int tcnt = g_cnt.triv;
        int ntriv = gridDim.x - nl;
        for (int c = blockIdx.x - nl; c * 512 < tcnt; c += ntriv) {
            int ti = c * 512 + tid;
            if (ti >= tcnt) continue;
            int i = g_tidx[ti];
            float r[32];
            load32(r, emb + (size_t)x[i * 16] * 32);
            float cb[32];
#pragma unroll
            for (int m = 0; m < 32; ++m) {
                float acc = bcv[m];
                const float4* wv4 = reinterpret_cast<const float4*>(Wc + m * 96);
#pragma unroll
                for (int k = 0; k < 8; ++k) {
                    float4 wv = wv4[k];
                    acc = fmaf(wv.x, r[4*k], acc);   acc = fmaf(wv.y, r[4*k+1], acc);
                    acc = fmaf(wv.z, r[4*k+2], acc); acc = fmaf(wv.w, r[4*k+3], acc);
                }
                cb[m] = fmaxf(acc, 0.0f);
            }
            float lg[64], mx = -1e30f;
#pragma unroll
            for (int m = 0; m < 64; ++m) {
                float acc = btv[m];
                const float4* wv4 = reinterpret_cast<const float4*>(Wt + m * 32);
#pragma unroll
                for (int k = 0; k < 8; ++k) {
                    float4 wv = wv4[k];
                    acc = fmaf(wv.x, cb[4*k], acc);   acc = fmaf(wv.y, cb[4*k+1], acc);
                    acc = fmaf(wv.z, cb[4*k+2], acc); acc = fmaf(wv.w, cb[4*k+3], acc);
                }
                lg[m] = acc; mx = fmaxf(mx, acc);
            }
            float se = 0.0f;
#pragma unroll
            for (int m = 0; m < 64; ++m) se += __expf(lg[m] - mx);
            float lse = mx + logf(se);
            float4* o4 = reinterpret_cast<float4*>(out + (size_t)i * 64);
#pragma unroll
            for (int cc = 0; cc < 16; ++cc) {
                float4 v;
                v.x = lg[4*cc]-lse; v.y = lg[4*cc+1]-lse;
                v.z = lg[4*cc+2]-lse; v.w = lg[4*cc+3]-lse;
                o4[cc] = v;
            }
        }
        return;
    }

    // ------------------------- LSTM path ------------------------------------
    extern __shared__ char smraw[];
    SmemB* sm = reinterpret_cast<SmemB*>(smraw);

    int lane = tid & 31;
    int w = tid >> 5;          // 0..15
    int j0 = w * 4;            // 4 rows per warp
    int e0 = lane, e1 = lane + 32;
    int gA = blockIdx.x * 64 + e0, gB = gA + 32;
    bool actA = gA < cnt, actB = gB < cnt;
    int iA = g_idx[actA ? gA : (cnt - 1)];
    int iB = g_idx[actB ? gB : (cnt - 1)];

    // x stager identity (tid<256): 4 threads/elem, pg = 8-float chunk
    int ep = tid & 63, pg = (tid >> 6) & 3;
    bool stager = tid < 256;
    int gp = blockIdx.x * 64 + ep;
    const int* xrP = x + (size_t)g_idx[gp < cnt ? gp : (cnt - 1)] * 16;

    u32 xpbase = smem_u32(&sm->xp[0][0][0]);
    u32 xrbase = smem_u32(&sm->xroot[0][0]);
    u32 stoff = ((pg * 4) * 64 + ep) * 8;   // this thread's 4 kpair slots

    // stage step-0 x into xp[0] via cp.async
    if (stager) {
        const char* src = (const char*)emb + (size_t)xrP[0] * 128 + pg * 32;
        u32 dst = xpbase + stoff;
#pragma unroll
        for (int c = 0; c < 4; ++c) cpa8(dst + c * 512, src + c * 8);
        CPA_COMMIT();
    }

    // ---- shared init (weights etc.) ----
    for (int idx = tid; idx < 48 * 64; idx += 512) {
        int kk = idx >> 6, j = idx & 63;
        float wi0, wi1, wf0, wf1, wg0, wg1, wo0, wo1;
        if (kk < 16) {
            int c = 2*kk;
            wi0 = Wih[j*32 + c];          wi1 = Wih[j*32 + c + 1];
            wf0 = Wih[(64 + j)*32 + c];   wf1 = Wih[(64 + j)*32 + c + 1];
            wg0 = Wih[(128 + j)*32 + c];  wg1 = Wih[(128 + j)*32 + c + 1];
            wo0 = Wih[(192 + j)*32 + c];  wo1 = Wih[(192 + j)*32 + c + 1];
        } else {
            int c = 2*kk - 32;
            wi0 = Whh[j*64 + c];          wi1 = Whh[j*64 + c + 1];
            wf0 = Whh[(64 + j)*64 + c];   wf1 = Whh[(64 + j)*64 + c + 1];
            wg0 = Whh[(128 + j)*64 + c];  wg1 = Whh[(128 + j)*64 + c + 1];
            wo0 = Whh[(192 + j)*64 + c];  wo1 = Whh[(192 + j)*64 + c + 1];
        }
        ulonglong2 vif, vgo;
        vif.x = packf2(wi0, wi1); vif.y = packf2(wf0, wf1);
        vgo.x = packf2(wg0, wg1); vgo.y = packf2(wo0, wo1);
        sm->Wif[kk][j] = vif;
        sm->Wgo[kk][j] = vgo;
    }
    if (tid < 64) {
        int j = tid;
        float bi = bih[j] + bhh[j];
        float bf = bih[64 + j] + bhh[64 + j];
        float bg = bih[128 + j] + bhh[128 + j];
        float bo = bih[192 + j] + bhh[192 + j];
        float ai = bi, af = bf, ag = bg, ao = bo;
        for (int k = 0; k < 64; ++k) {
            float hk = h0[k];
            ai = fmaf(Whh[j*64 + k], hk, ai);
            af = fmaf(Whh[(64 + j)*64 + k], hk, af);
            ag = fmaf(Whh[(128 + j)*64 + k], hk, ag);
            ao = fmaf(Whh[(192 + j)*64 + k], hk, ao);
        }
        sm->bIF[j]  = make_float2(bi, bf);
        sm->bGO[j]  = make_float2(bg, bo);
        sm->a0IF[j] = make_float2(ai, af);
        sm->a0GO[j] = make_float2(ag, ao);
        sm->c0s[j] = c0[j];
        sm->bt[j] = btv[j];
    }
    for (int idx = tid; idx < 32 * 48; idx += 512) {
        int m = idx / 48, kk = idx % 48;
        sm->Wc2[idx] = packf2(Wc[m*96 + 2*kk], Wc[m*96 + 2*kk + 1]);
    }
    for (int idx = tid; idx < 64 * 16; idx += 512) {
        int m = idx / 16, kk = idx % 16;
        sm->Wt2[idx] = packf2(Wt[m*32 + 2*kk], Wt[m*32 + 2*kk + 1]);
    }
    if (tid < 32) sm->bc[tid] = bcv[tid];
    CPA_WAIT0();
    __syncthreads();

    float cA[4], cB[4];

#pragma unroll 1
    for (int bp = 0; bp < 5; ++bp) {
#pragma unroll 1
        for (int t = 0; t < 4; ++t) {
            int step = 4*bp + t;
            int b = step & 1;

            // stagers: async-stage next x into the OTHER xp buffer
            if (stager && step + 1 < 16) {
                const char* src = (const char*)emb + (size_t)xrP[step + 1] * 128 + pg * 32;
                u32 dst = xpbase + (u32)(((step + 1) & 1) * 8192) + stoff;
#pragma unroll
                for (int c = 0; c < 4; ++c) cpa8(dst + c * 512, src + c * 8);
                CPA_COMMIT();
            }
            // bp4 root = emb[x[0]] -> xroot (async)
            if (stager && bp == 4 && t == 0) {
                const char* src = (const char*)emb + (size_t)xrP[0] * 128 + pg * 32;
                u32 dst = xrbase + stoff;
#pragma unroll
                for (int c = 0; c < 4; ++c) cpa8(dst + c * 512, src + c * 8);
                CPA_COMMIT();
            }

            const u64* ops = (bp < 4) ? &sm->xp[b][0][0] : &sm->xbig[t][0][0];
            const u64* hrd = &sm->hp[b ^ 1][0][0];   // written at step-1
            const float2* preIF = (t == 0) ? sm->a0IF : sm->bIF;
            const float2* preGO = (t == 0) ? sm->a0GO : sm->bGO;

            // ---- fused gate pass: 4 rows x 4 gates x 2 elems ----
            u64 acc[4][4][2];   // [row][i,f,g,o][elemA/B]
#pragma unroll
            for (int r = 0; r < 4; ++r) {
                float2 pif = preIF[j0 + r], pgo = preGO[j0 + r];
                acc[r][0][0] = packf2(pif.x, 0.f); acc[r][0][1] = acc[r][0][0];
                acc[r][1][0] = packf2(pif.y, 0.f); acc[r][1][1] = acc[r][1][0];
                acc[r][2][0] = packf2(pgo.x, 0.f); acc[r][2][1] = acc[r][2][0];
                acc[r][3][0] = packf2(pgo.y, 0.f); acc[r][3][1] = acc[r][3][0];
            }
#pragma unroll 4
            for (int kk = 0; kk < 16; ++kk) {
                u64 oA = ops[kk*64 + e0], oB = ops[kk*64 + e1];
#pragma unroll
                for (int r = 0; r < 4; ++r) {
                    ulonglong2 wif = sm->Wif[kk][j0 + r];
                    ulonglong2 wgo = sm->Wgo[kk][j0 + r];
                    ffma2(acc[r][0][0], wif.x, oA); ffma2(acc[r][1][0], wif.y, oA);
                    ffma2(acc[r][2][0], wgo.x, oA); ffma2(acc[r][3][0], wgo.y, oA);
                    ffma2(acc[r][0][1], wif.x, oB); ffma2(acc[r][1][1], wif.y, oB);
                    ffma2(acc[r][2][1], wgo.x, oB); ffma2(acc[r][3][1], wgo.y, oB);
                }
            }
            if (t > 0) {
#pragma unroll 4
                for (int kk = 0; kk < 32; ++kk) {
                    u64 oA = hrd[kk*64 + e0], oB = hrd[kk*64 + e1];
#pragma unroll
                    for (int r = 0; r < 4; ++r) {
                        ulonglong2 wif = sm->Wif[16 + kk][j0 + r];
                        ulonglong2 wgo = sm->Wgo[16 + kk][j0 + r];
                        ffma2(acc[r][0][0], wif.x, oA); ffma2(acc[r][1][0], wif.y, oA);
                        ffma2(acc[r][2][0], wgo.x, oA); ffma2(acc[r][3][0], wgo.y, oA);
                        ffma2(acc[r][0][1], wif.x, oB); ffma2(acc[r][1][1], wif.y, oB);
                        ffma2(acc[r][2][1], wgo.x, oB); ffma2(acc[r][3][1], wgo.y, oB);
                    }
                }
            }

            // activations + c update + h write to the OTHER hp buffer (no WAR)
            float* hwf = reinterpret_cast<float*>(&sm->hp[b][0][0]);
#pragma unroll
            for (int r = 0; r < 4; ++r) {
                int j = j0 + r;
                {
                    float iv = fsig(hsum2(acc[r][0][0]));
                    float fv = fsig(hsum2(acc[r][1][0]));
                    float gv = ftanh_(hsum2(acc[r][2][0]));
                    float ov = fsig(hsum2(acc[r][3][0]));
                    float cp = (t == 0) ? sm->c0s[j] : cA[r];
                    float cc = fmaf(fv, cp, iv * gv);
                    cA[r] = cc;
                    float hn = ov * ftanh_(cc);
                    hwf[((j >> 1)*64 + e0)*2 + (j & 1)] = (t == 3) ? fmaxf(hn, 0.f) : hn;
                }
                {
                    float iv = fsig(hsum2(acc[r][0][1]));
                    float fv = fsig(hsum2(acc[r][1][1]));
                    float gv = ftanh_(hsum2(acc[r][2][1]));
                    float ov = fsig(hsum2(acc[r][3][1]));
                    float cp = (t == 0) ? sm->c0s[j] : cB[r];
                    float cc = fmaf(fv, cp, iv * gv);
                    cB[r] = cc;
                    float hn = ov * ftanh_(cc);
                    hwf[((j >> 1)*64 + e1)*2 + (j & 1)] = (t == 3) ? fmaxf(hn, 0.f) : hn;
                }
            }
            // root snapshot: copy CURRENT x (xp[0], b==0 at t==0) -> xroot.
            // cp.async this step writes xp[1]; no overlap.
            if (t == 0 && bp < 4 && stager) {
                const u64* s0 = &sm->xp[0][0][0];
                u64* d0 = &sm->xroot[0][0];
#pragma unroll
                for (int c = 0; c < 4; ++c) d0[tid*4 + c] = s0[tid*4 + c];
            }
            CPA_WAIT0();       // next-x (and bp4 root) landed
            __syncthreads();   // single per-step barrier
        }

        // ---- comb = relu(Wc @ [root, last] + bc); last in hp[1] (odd step) ----
        {
            int m0 = w * 2;
            u64 ac[2][2];
#pragma unroll
            for (int mr = 0; mr < 2; ++mr) {
                ac[mr][0] = packf2(sm->bc[m0 + mr], 0.f);
                ac[mr][1] = ac[mr][0];
            }
            const u64* xr_ = &sm->xroot[0][0];
#pragma unroll 4
            for (int kk = 0; kk < 16; ++kk) {
                u64 oA = xr_[kk*64 + e0], oB = xr_[kk*64 + e1];
#pragma unroll
                for (int mr = 0; mr < 2; ++mr) {
                    u64 wv = sm->Wc2[(m0 + mr)*48 + kk];
                    ffma2(ac[mr][0], wv, oA); ffma2(ac[mr][1], wv, oB);
                }
            }
            const u64* hrd = &sm->hp[1][0][0];
#pragma unroll 4
            for (int kk = 0; kk < 32; ++kk) {
                u64 oA = hrd[kk*64 + e0], oB = hrd[kk*64 + e1];
#pragma unroll
                for (int mr = 0; mr < 2; ++mr) {
                    u64 wv = sm->Wc2[(m0 + mr)*48 + 16 + kk];
                    ffma2(ac[mr][0], wv, oA); ffma2(ac[mr][1], wv, oB);
                }
            }
            float* xbf = reinterpret_cast<float*>(&sm->xbig[bp][0][0]);
#pragma unroll
            for (int mr = 0; mr < 2; ++mr) {
                int m = m0 + mr;
                xbf[((m >> 1)*64 + e0)*2 + (m & 1)] = fmaxf(hsum2(ac[mr][0]), 0.f);
                xbf[((m >> 1)*64 + e1)*2 + (m & 1)] = fmaxf(hsum2(ac[mr][1]), 0.f);
            }
            __syncthreads();
        }
    }

    // ---- logits + log_softmax (4 tags per warp) ----
    {
        int m0 = w * 4;
        u64 lA[4], lB[4];
#pragma unroll
        for (int mr = 0; mr < 4; ++mr) {
            lA[mr] = packf2(sm->bt[m0 + mr], 0.f);
            lB[mr] = lA[mr];
        }
        const u64* cbr = &sm->xbig[4][0][0];
#pragma unroll 4
        for (int kk = 0; kk < 16; ++kk) {
            u64 oA = cbr[kk*64 + e0], oB = cbr[kk*64 + e1];
#pragma unroll
            for (int mr = 0; mr < 4; ++mr) {
                u64 wv = sm->Wt2[(m0 + mr)*16 + kk];
                ffma2(lA[mr], wv, oA); ffma2(lB[mr], wv, oB);
            }
        }
        float lgA[4], lgB[4], mxA = -1e30f, mxB = -1e30f;
#pragma unroll
        for (int mr = 0; mr < 4; ++mr) {
            lgA[mr] = hsum2(lA[mr]); mxA = fmaxf(mxA, lgA[mr]);
            lgB[mr] = hsum2(lB[mr]); mxB = fmaxf(mxB, lgB[mr]);
        }
        float* red = reinterpret_cast<float*>(&sm->xroot[0][0]);
        red[w*64 + e0] = mxA;
        red[w*64 + e1] = mxB;
        __syncthreads();
        float fmxA = -1e30f, fmxB = -1e30f;
#pragma unroll
        for (int k = 0; k < 16; ++k) {
            fmxA = fmaxf(fmxA, red[k*64 + e0]);
            fmxB = fmaxf(fmxB, red[k*64 + e1]);
        }
        float seA = 0.f, seB = 0.f;
#pragma unroll
        for (int mr = 0; mr < 4; ++mr) {
            seA += __expf(lgA[mr] - fmxA);
            seB += __expf(lgB[mr] - fmxB);
        }
        red[1024 + w*64 + e0] = seA;
        red[1024 + w*64 + e1] = seB;
        __syncthreads();
        float tseA = 0.f, tseB = 0.f;
#pragma unroll
        for (int k = 0; k < 16; ++k) {
            tseA += red[1024 + k*64 + e0];
            tseB += red[1024 + k*64 + e1];
        }
        float lseA = fmxA + logf(tseA);
        float lseB = fmxB + logf(tseB);
        if (actA) {
            float4 v;
            v.x = lgA[0]-lseA; v.y = lgA[1]-lseA; v.z = lgA[2]-lseA; v.w = lgA[3]-lseA;
            *reinterpret_cast<float4*>(out + (size_t)iA * 64 + m0) = v;
        }
        if (actB) {
            float4 v;
            v.x = lgB[0]-lseB; v.y = lgB[1]-lseB; v.z = lgB[2]-lseB; v.w = lgB[3]-lseB;
            *reinterpret_cast<float4*>(out + (size_t)iB * 64 + m0) = v;
        }
    }
}

// ---------------------------------------------------------------------------
extern "C" void kernel_launch(void* const* d_in, const int* in_sizes, int n_in,
                              void* d_out, int out_size)
{
    const int*   x   = (const int*)d_in[0];
    const int*   s   = (const int*)d_in[1];
    const float* emb = (const float*)d_in[2];
    const float* Wih = (const float*)d_in[3];
    const float* Whh = (const float*)d_in[4];
    const float* bih = (const float*)d_in[5];
    const float* bhh = (const float*)d_in[6];
    const float* h0  = (const float*)d_in[7];
    const float* c0  = (const float*)d_in[8];
    const float* Wc  = (const float*)d_in[9];
    const float* bc  = (const float*)d_in[10];
    const float* Wt  = (const float*)d_in[11];
    const float* bt  = (const float*)d_in[12];
    float* out = (float*)d_out;

    int B = in_sizes[1];
    if (B > MAXB) B = MAXB;

    cudaFuncSetAttribute(k_main, cudaFuncAttributeMaxDynamicSharedMemorySize,
                         (int)sizeof(SmemB));

    void* cptr = nullptr;
    cudaGetSymbolAddress(&cptr, g_cnt);
    cudaMemsetAsync(cptr, 0, sizeof(Counters));

    k_compact<<<(B + 255) / 256, 256>>>(s, B);
    int nblk = (B + 63) / 64;
    k_main<<<nblk, 512, sizeof(SmemB)>>>(x, emb, Wih, Whh, bih, bhh,
                                         h0, c0, Wc, bc, Wt, bt, out, B);
}